// round 1
// baseline (speedup 1.0000x reference)
#include <cuda_runtime.h>

#define BATCH 8
#define SEQ   1024
#define DIM   768
#define EPS_F 1e-7f

// Scratch (allocation-free rule: __device__ globals)
__device__ float g_E[(size_t)BATCH * SEQ * SEQ];        // exp(QK^T)*mask, 33.5 MB
__device__ float g_partial[(size_t)BATCH * SEQ * 8];    // per-(row, colblock) partial sums
__device__ float g_den[(size_t)BATCH * SEQ];            // row denominators (+EPS)

// ---------------------------------------------------------------------------
// Kernel 1: E = exp(A A^T) * m_row * m_col, plus partial row sums.
// 128x128 block tile, BK=16, 256 threads, 8x8 microtile per thread.
// ---------------------------------------------------------------------------
__global__ void __launch_bounds__(256) qk_exp_kernel(const float* __restrict__ A,
                                                     const int*   __restrict__ mask)
{
    const int b       = blockIdx.z;
    const int rowBase = blockIdx.y * 128;
    const int colBase = blockIdx.x * 128;
    const float* Ab = A + (size_t)b * SEQ * DIM;

    __shared__ float As[16][128];
    __shared__ float Bs[16][128];

    const int tid = threadIdx.x;
    const int tr  = tid >> 4;   // 0..15
    const int tc  = tid & 15;   // 0..15

    float acc[8][8];
    #pragma unroll
    for (int i = 0; i < 8; i++)
        #pragma unroll
        for (int j = 0; j < 8; j++) acc[i][j] = 0.f;

    for (int k0 = 0; k0 < DIM; k0 += 16) {
        #pragma unroll
        for (int l = 0; l < 2; l++) {
            int idx = tid + l * 256;          // 0..511
            int r   = idx >> 2;               // 0..127
            int c4  = (idx & 3) << 2;         // 0,4,8,12
            float4 va = *(const float4*)(Ab + (size_t)(rowBase + r) * DIM + k0 + c4);
            As[c4 + 0][r] = va.x; As[c4 + 1][r] = va.y;
            As[c4 + 2][r] = va.z; As[c4 + 3][r] = va.w;
            float4 vb = *(const float4*)(Ab + (size_t)(colBase + r) * DIM + k0 + c4);
            Bs[c4 + 0][r] = vb.x; Bs[c4 + 1][r] = vb.y;
            Bs[c4 + 2][r] = vb.z; Bs[c4 + 3][r] = vb.w;
        }
        __syncthreads();
        #pragma unroll
        for (int k = 0; k < 16; k++) {
            float a[8], bv[8];
            #pragma unroll
            for (int i = 0; i < 8; i++) a[i]  = As[k][tr * 8 + i];
            #pragma unroll
            for (int j = 0; j < 8; j++) bv[j] = Bs[k][tc * 8 + j];
            #pragma unroll
            for (int i = 0; i < 8; i++)
                #pragma unroll
                for (int j = 0; j < 8; j++)
                    acc[i][j] = fmaf(a[i], bv[j], acc[i][j]);
        }
        __syncthreads();
    }

    // Epilogue: exp, mask, store E, reduce row sums across the 16 tc lanes.
    float mcol[8];
    #pragma unroll
    for (int j = 0; j < 8; j++)
        mcol[j] = (float)mask[b * SEQ + colBase + tc * 8 + j];

    #pragma unroll
    for (int i = 0; i < 8; i++) {
        const int row  = rowBase + tr * 8 + i;
        const float mrow = (float)mask[b * SEQ + row];
        float e[8];
        float rowsum = 0.f;
        #pragma unroll
        for (int j = 0; j < 8; j++) {
            e[j] = __expf(acc[i][j]) * mrow * mcol[j];
            rowsum += e[j];
        }
        float* Erow = g_E + ((size_t)b * SEQ + row) * SEQ + colBase + tc * 8;
        *(float4*)(Erow)     = make_float4(e[0], e[1], e[2], e[3]);
        *(float4*)(Erow + 4) = make_float4(e[4], e[5], e[6], e[7]);

        // reduce over the 16 tc lanes (tids tr*16 .. tr*16+15 sit in one warp half)
        #pragma unroll
        for (int off = 8; off > 0; off >>= 1)
            rowsum += __shfl_down_sync(0xffffffffu, rowsum, off, 16);
        if (tc == 0)
            g_partial[((size_t)b * SEQ + row) * 8 + blockIdx.x] = rowsum;
    }
}

// ---------------------------------------------------------------------------
// Kernel 2: deterministic denominator reduction (no float atomics).
// ---------------------------------------------------------------------------
__global__ void reduce_den_kernel()
{
    int i = blockIdx.x * blockDim.x + threadIdx.x;
    if (i < BATCH * SEQ) {
        float s = EPS_F;
        #pragma unroll
        for (int j = 0; j < 8; j++) s += g_partial[(size_t)i * 8 + j];
        g_den[i] = s;
    }
}

// ---------------------------------------------------------------------------
// Kernel 3: out = (E @ A) / den.  Same SGEMM core; V tile loads are naturally
// coalesced ([16 x 128] row-major), E tile stored transposed like kernel 1.
// ---------------------------------------------------------------------------
__global__ void __launch_bounds__(256) pv_kernel(const float* __restrict__ A,
                                                 float* __restrict__ out)
{
    const int b       = blockIdx.z;
    const int rowBase = blockIdx.y * 128;   // S rows
    const int colBase = blockIdx.x * 128;   // D cols
    const float* Ab = A   + (size_t)b * SEQ * DIM;
    const float* Eb = g_E + (size_t)b * SEQ * SEQ;

    __shared__ float Es[16][128];
    __shared__ float Vs[16][128];

    const int tid = threadIdx.x;
    const int tr  = tid >> 4;
    const int tc  = tid & 15;

    float acc[8][8];
    #pragma unroll
    for (int i = 0; i < 8; i++)
        #pragma unroll
        for (int j = 0; j < 8; j++) acc[i][j] = 0.f;

    for (int k0 = 0; k0 < SEQ; k0 += 16) {
        #pragma unroll
        for (int l = 0; l < 2; l++) {
            int idx = tid + l * 256;          // 0..511
            // E tile [128 rows x 16 k], transposed into Es[k][row]
            int r  = idx >> 2;
            int c4 = (idx & 3) << 2;
            float4 ve = *(const float4*)(Eb + (size_t)(rowBase + r) * SEQ + k0 + c4);
            Es[c4 + 0][r] = ve.x; Es[c4 + 1][r] = ve.y;
            Es[c4 + 2][r] = ve.z; Es[c4 + 3][r] = ve.w;
            // V tile [16 k x 128 cols], direct
            int kr = idx >> 5;                // 0..15
            int cc = (idx & 31) << 2;         // 0..124
            float4 vv = *(const float4*)(Ab + (size_t)(k0 + kr) * DIM + colBase + cc);
            *(float4*)&Vs[kr][cc] = vv;
        }
        __syncthreads();
        #pragma unroll
        for (int k = 0; k < 16; k++) {
            float a[8], bv[8];
            #pragma unroll
            for (int i = 0; i < 8; i++) a[i]  = Es[k][tr * 8 + i];
            #pragma unroll
            for (int j = 0; j < 8; j++) bv[j] = Vs[k][tc * 8 + j];
            #pragma unroll
            for (int i = 0; i < 8; i++)
                #pragma unroll
                for (int j = 0; j < 8; j++)
                    acc[i][j] = fmaf(a[i], bv[j], acc[i][j]);
        }
        __syncthreads();
    }

    #pragma unroll
    for (int i = 0; i < 8; i++) {
        const int row = rowBase + tr * 8 + i;
        const float inv = 1.0f / g_den[(size_t)b * SEQ + row];
        float* orow = out + ((size_t)b * SEQ + row) * DIM + colBase + tc * 8;
        *(float4*)(orow)     = make_float4(acc[i][0] * inv, acc[i][1] * inv,
                                           acc[i][2] * inv, acc[i][3] * inv);
        *(float4*)(orow + 4) = make_float4(acc[i][4] * inv, acc[i][5] * inv,
                                           acc[i][6] * inv, acc[i][7] * inv);
    }
}

// ---------------------------------------------------------------------------
extern "C" void kernel_launch(void* const* d_in, const int* in_sizes, int n_in,
                              void* d_out, int out_size)
{
    const float* A    = (const float*)d_in[0];
    const int*   mask = (const int*)d_in[1];
    float*       out  = (float*)d_out;

    dim3 g1(SEQ / 128, SEQ / 128, BATCH);   // 8 x 8 x 8
    qk_exp_kernel<<<g1, 256>>>(A, mask);

    reduce_den_kernel<<<(BATCH * SEQ + 255) / 256, 256>>>();

    dim3 g2(DIM / 128, SEQ / 128, BATCH);   // 6 x 8 x 8
    pv_kernel<<<g2, 256>>>(A, out);
}

// round 3
// speedup vs baseline: 2.3373x; 2.3373x over previous
#include <cuda_runtime.h>
#include <cstdint>

#define BATCH 8
#define SEQ   1024
#define DIM   768
#define EPS_F 1e-7f

#define BM 128
#define BN 128
#define BK 16
#define PADK 20          // padded k-stride (floats): conflict-free frag loads

// Scratch (allocation-free rule: __device__ globals)
__device__ float g_E[(size_t)BATCH * SEQ * SEQ];        // exp(QK^T)*mask
__device__ float g_partial[(size_t)BATCH * SEQ * 32];   // per-(row, colblk*4+warpcol)
__device__ float g_den[(size_t)BATCH * SEQ];

// fp32 -> tf32 round-to-nearest (unbiased)
__device__ __forceinline__ uint32_t f2tf(float x) {
    uint32_t u; asm("cvt.rna.tf32.f32 %0, %1;" : "=r"(u) : "f"(x)); return u;
}

__device__ __forceinline__ void mma_tf32(float c[4],
                                         uint32_t a0, uint32_t a1, uint32_t a2, uint32_t a3,
                                         uint32_t b0, uint32_t b1) {
    asm("mma.sync.aligned.m16n8k8.row.col.f32.tf32.tf32.f32 "
        "{%0,%1,%2,%3}, {%4,%5,%6,%7}, {%8,%9}, {%0,%1,%2,%3};"
        : "+f"(c[0]), "+f"(c[1]), "+f"(c[2]), "+f"(c[3])
        : "r"(a0), "r"(a1), "r"(a2), "r"(a3), "r"(b0), "r"(b1));
}

// convert float4 -> tf32 uint4
__device__ __forceinline__ uint4 cvt4(float4 v) {
    return make_uint4(f2tf(v.x), f2tf(v.y), f2tf(v.z), f2tf(v.w));
}

// ---------------------------------------------------------------------------
// Shared compute core: 128x128 tile, 8 warps (2x4), 4x4 m16n8 tiles per warp.
// As/Bs layouts: [row][k] with PADK stride => all frag LDS are conflict-free.
// ---------------------------------------------------------------------------
#define COMPUTE_TILE(AsBuf, BsBuf)                                            \
    _Pragma("unroll")                                                         \
    for (int ks = 0; ks < 2; ks++) {                                          \
        uint32_t bf[4][2];                                                    \
        _Pragma("unroll")                                                     \
        for (int nt = 0; nt < 4; nt++) {                                      \
            int bb = (nBase + nt * 8 + qid) * PADK + ks * 8 + tq;             \
            bf[nt][0] = (BsBuf)[bb];                                          \
            bf[nt][1] = (BsBuf)[bb + 4];                                      \
        }                                                                     \
        _Pragma("unroll")                                                     \
        for (int mt = 0; mt < 4; mt++) {                                      \
            int ab = (mBase + mt * 16 + qid) * PADK + ks * 8 + tq;            \
            uint32_t a0 = (AsBuf)[ab];                                        \
            uint32_t a1 = (AsBuf)[ab + 8 * PADK];                             \
            uint32_t a2 = (AsBuf)[ab + 4];                                    \
            uint32_t a3 = (AsBuf)[ab + 8 * PADK + 4];                         \
            _Pragma("unroll")                                                 \
            for (int nt = 0; nt < 4; nt++)                                    \
                mma_tf32(acc[mt][nt], a0, a1, a2, a3, bf[nt][0], bf[nt][1]);  \
        }                                                                     \
    }

// ---------------------------------------------------------------------------
// Kernel 1: E = exp(A A^T) * m_row * m_col, plus partial row sums.
// ---------------------------------------------------------------------------
__global__ void __launch_bounds__(256, 2) qk_exp_mma(const float* __restrict__ A,
                                                     const int*   __restrict__ mask)
{
    __shared__ uint32_t As[2][BM * PADK];
    __shared__ uint32_t Bs[2][BN * PADK];

    const int b       = blockIdx.z;
    const int rowBase = blockIdx.y * BM;
    const int colBase = blockIdx.x * BN;
    const float* Ab = A + (size_t)b * SEQ * DIM;
    const int bS = b * SEQ;

    const int tid  = threadIdx.x;
    const int wid  = tid >> 5;
    const int lane = tid & 31;
    const int qid  = lane >> 2;   // 0..7
    const int tq   = lane & 3;    // 0..3
    const int mBase = (wid >> 2) * 64;
    const int nBase = (wid & 3) * 32;

    const int r_ld  = tid >> 2;           // 0..63  (+64 for second load)
    const int c4_ld = (tid & 3) << 2;     // 0,4,8,12

    float acc[4][4][4];
    #pragma unroll
    for (int i = 0; i < 4; i++)
        #pragma unroll
        for (int j = 0; j < 4; j++)
            #pragma unroll
            for (int k = 0; k < 4; k++) acc[i][j][k] = 0.f;

    const int NT = DIM / BK;   // 48

    // prologue: tile 0
    {
        #pragma unroll
        for (int l = 0; l < 2; l++) {
            int r = r_ld + l * 64;
            float4 va = *(const float4*)(Ab + (size_t)(rowBase + r) * DIM + c4_ld);
            float4 vb = *(const float4*)(Ab + (size_t)(colBase + r) * DIM + c4_ld);
            *(uint4*)&As[0][r * PADK + c4_ld] = cvt4(va);
            *(uint4*)&Bs[0][r * PADK + c4_ld] = cvt4(vb);
        }
    }
    __syncthreads();

    for (int it = 0; it < NT; it++) {
        const int buf = it & 1;
        float4 pA[2], pB[2];
        if (it + 1 < NT) {
            const int k0 = (it + 1) * BK;
            #pragma unroll
            for (int l = 0; l < 2; l++) {
                int r = r_ld + l * 64;
                pA[l] = *(const float4*)(Ab + (size_t)(rowBase + r) * DIM + k0 + c4_ld);
                pB[l] = *(const float4*)(Ab + (size_t)(colBase + r) * DIM + k0 + c4_ld);
            }
        }

        COMPUTE_TILE(As[buf], Bs[buf]);

        if (it + 1 < NT) {
            #pragma unroll
            for (int l = 0; l < 2; l++) {
                int r = r_ld + l * 64;
                *(uint4*)&As[buf ^ 1][r * PADK + c4_ld] = cvt4(pA[l]);
                *(uint4*)&Bs[buf ^ 1][r * PADK + c4_ld] = cvt4(pB[l]);
            }
        }
        __syncthreads();
    }

    // Epilogue: exp * masks, store E, deterministic partial row sums.
    const int wc = wid & 3;
    #pragma unroll
    for (int mt = 0; mt < 4; mt++) {
        const int r0 = rowBase + mBase + mt * 16 + qid;
        const float mr0 = (float)mask[bS + r0];
        const float mr1 = (float)mask[bS + r0 + 8];
        float s0 = 0.f, s1 = 0.f;
        #pragma unroll
        for (int nt = 0; nt < 4; nt++) {
            const int cc = colBase + nBase + nt * 8 + tq * 2;
            const float mc0 = (float)mask[bS + cc];
            const float mc1 = (float)mask[bS + cc + 1];
            float e00 = __expf(acc[mt][nt][0]) * mr0 * mc0;
            float e01 = __expf(acc[mt][nt][1]) * mr0 * mc1;
            float e10 = __expf(acc[mt][nt][2]) * mr1 * mc0;
            float e11 = __expf(acc[mt][nt][3]) * mr1 * mc1;
            s0 += e00 + e01;
            s1 += e10 + e11;
            *(float2*)&g_E[((size_t)bS + r0) * SEQ + cc]     = make_float2(e00, e01);
            *(float2*)&g_E[((size_t)bS + r0 + 8) * SEQ + cc] = make_float2(e10, e11);
        }
        // reduce across the 4 tq lanes (same row)
        s0 += __shfl_xor_sync(0xffffffffu, s0, 1);
        s0 += __shfl_xor_sync(0xffffffffu, s0, 2);
        s1 += __shfl_xor_sync(0xffffffffu, s1, 1);
        s1 += __shfl_xor_sync(0xffffffffu, s1, 2);
        if (tq == 0) {
            g_partial[((size_t)bS + r0) * 32 + blockIdx.x * 4 + wc]       = s0;
            g_partial[((size_t)bS + r0 + 8) * 32 + blockIdx.x * 4 + wc]   = s1;
        }
    }
}

// ---------------------------------------------------------------------------
// Kernel 2: deterministic denominator reduction.
// ---------------------------------------------------------------------------
__global__ void reduce_den_kernel()
{
    int i = blockIdx.x * blockDim.x + threadIdx.x;
    if (i < BATCH * SEQ) {
        float s = EPS_F;
        #pragma unroll
        for (int j = 0; j < 32; j++) s += g_partial[(size_t)i * 32 + j];
        g_den[i] = s;
    }
}

// ---------------------------------------------------------------------------
// Kernel 3: out = (E @ A) / den.
// ---------------------------------------------------------------------------
__global__ void __launch_bounds__(256, 2) pv_mma(const float* __restrict__ A,
                                                 float* __restrict__ out)
{
    __shared__ uint32_t Es[2][BM * PADK];
    __shared__ uint32_t Vs[2][BN * PADK];

    const int b       = blockIdx.z;
    const int rowBase = blockIdx.y * BM;   // S rows
    const int colBase = blockIdx.x * BN;   // D cols
    const float* Ab = A   + (size_t)b * SEQ * DIM;
    const float* Eb = g_E + (size_t)b * SEQ * SEQ;
    const int bS = b * SEQ;

    const int tid  = threadIdx.x;
    const int wid  = tid >> 5;
    const int lane = tid & 31;
    const int qid  = lane >> 2;
    const int tq   = lane & 3;
    const int mBase = (wid >> 2) * 64;
    const int nBase = (wid & 3) * 32;

    const int r_ld  = tid >> 2;
    const int c4_ld = (tid & 3) << 2;
    const int kk_ld = tid & 15;            // 0..15 (V transpose load)
    const int n4_ld = (tid >> 4) << 2;     // 0..60 (+64 for second)

    float acc[4][4][4];
    #pragma unroll
    for (int i = 0; i < 4; i++)
        #pragma unroll
        for (int j = 0; j < 4; j++)
            #pragma unroll
            for (int k = 0; k < 4; k++) acc[i][j][k] = 0.f;

    const int NT = SEQ / BK;   // 64

    // prologue
    {
        #pragma unroll
        for (int l = 0; l < 2; l++) {
            int r = r_ld + l * 64;
            float4 ve = *(const float4*)(Eb + (size_t)(rowBase + r) * SEQ + c4_ld);
            *(uint4*)&Es[0][r * PADK + c4_ld] = cvt4(ve);
            int n4 = n4_ld + l * 64;
            float4 vv = *(const float4*)(Ab + (size_t)kk_ld * DIM + colBase + n4);
            Vs[0][(n4 + 0) * PADK + kk_ld] = f2tf(vv.x);
            Vs[0][(n4 + 1) * PADK + kk_ld] = f2tf(vv.y);
            Vs[0][(n4 + 2) * PADK + kk_ld] = f2tf(vv.z);
            Vs[0][(n4 + 3) * PADK + kk_ld] = f2tf(vv.w);
        }
    }
    __syncthreads();

    for (int it = 0; it < NT; it++) {
        const int buf = it & 1;
        float4 pE[2], pV[2];
        if (it + 1 < NT) {
            const int k0 = (it + 1) * BK;
            #pragma unroll
            for (int l = 0; l < 2; l++) {
                int r = r_ld + l * 64;
                pE[l] = *(const float4*)(Eb + (size_t)(rowBase + r) * SEQ + k0 + c4_ld);
                int n4 = n4_ld + l * 64;
                pV[l] = *(const float4*)(Ab + (size_t)(k0 + kk_ld) * DIM + colBase + n4);
            }
        }

        COMPUTE_TILE(Es[buf], Vs[buf]);

        if (it + 1 < NT) {
            #pragma unroll
            for (int l = 0; l < 2; l++) {
                int r = r_ld + l * 64;
                *(uint4*)&Es[buf ^ 1][r * PADK + c4_ld] = cvt4(pE[l]);
                int n4 = n4_ld + l * 64;
                Vs[buf ^ 1][(n4 + 0) * PADK + kk_ld] = f2tf(pV[l].x);
                Vs[buf ^ 1][(n4 + 1) * PADK + kk_ld] = f2tf(pV[l].y);
                Vs[buf ^ 1][(n4 + 2) * PADK + kk_ld] = f2tf(pV[l].z);
                Vs[buf ^ 1][(n4 + 3) * PADK + kk_ld] = f2tf(pV[l].w);
            }
        }
        __syncthreads();
    }

    // Epilogue: scale by 1/den, store.
    #pragma unroll
    for (int mt = 0; mt < 4; mt++) {
        const int r0 = rowBase + mBase + mt * 16 + qid;
        const float inv0 = 1.0f / g_den[bS + r0];
        const float inv1 = 1.0f / g_den[bS + r0 + 8];
        #pragma unroll
        for (int nt = 0; nt < 4; nt++) {
            const int cc = colBase + nBase + nt * 8 + tq * 2;
            *(float2*)&out[((size_t)bS + r0) * DIM + cc] =
                make_float2(acc[mt][nt][0] * inv0, acc[mt][nt][1] * inv0);
            *(float2*)&out[((size_t)bS + r0 + 8) * DIM + cc] =
                make_float2(acc[mt][nt][2] * inv1, acc[mt][nt][3] * inv1);
        }
    }
}

// ---------------------------------------------------------------------------
extern "C" void kernel_launch(void* const* d_in, const int* in_sizes, int n_in,
                              void* d_out, int out_size)
{
    const float* A    = (const float*)d_in[0];
    const int*   mask = (const int*)d_in[1];
    float*       out  = (float*)d_out;

    dim3 g1(SEQ / BN, SEQ / BM, BATCH);   // 8 x 8 x 8
    qk_exp_mma<<<g1, 256>>>(A, mask);

    reduce_den_kernel<<<(BATCH * SEQ + 255) / 256, 256>>>();

    dim3 g2(DIM / BN, SEQ / BM, BATCH);   // 6 x 8 x 8
    pv_mma<<<g2, 256>>>(A, out);
}